// round 2
// baseline (speedup 1.0000x reference)
#include <cuda_runtime.h>
#include <cuda_bf16.h>
#include <cstdint>

#define NN   50000
#define EE   800000
#define KIN  256
#define FOUT 128
#define NEG_ATT 0.2f
#define NEG_ACT 0.01f
#define BN_EPS  1e-5f

// Scratch (static device arrays — no allocations allowed)
__device__ __align__(16) float g_h[(size_t)NN * FOUT];   // projected features
__device__ __align__(16) float g_s[NN * 4];              // a_src per node/head
__device__ __align__(16) float g_d[NN * 4];              // a_dst per node/head
__device__ __align__(16) float g_den[NN * 4];            // softmax denominator
__device__ __align__(16) float g_stats[256];             // col sum[128], sumsq[128]

// ---------------------------------------------------------------------------
// Kernel 1: h = x @ W^T via 3xTF32 tensor-core mma (fp32-grade accuracy).
// Block tile 128x128, K chunked by 16. 8 warps in 4x2 (M x N) layout,
// warp tile 32x64 = 2 m16-tiles x 8 n8-tiles, mma.sync.m16n8k8.tf32.
// D = Ahi*Bhi + Ahi*Blo + Alo*Bhi  (lo*lo term ~2^-22, dropped).
// ---------------------------------------------------------------------------
__device__ __forceinline__ uint32_t f2tf(float f) {
    uint32_t r; asm("cvt.rna.tf32.f32 %0, %1;" : "=r"(r) : "f"(f)); return r;
}

#define MMA_TF32(D, A, B)                                                  \
    asm volatile("mma.sync.aligned.m16n8k8.row.col.f32.tf32.tf32.f32 "     \
                 "{%0,%1,%2,%3},{%4,%5,%6,%7},{%8,%9},{%0,%1,%2,%3};"      \
                 : "+f"(D[0]), "+f"(D[1]), "+f"(D[2]), "+f"(D[3])          \
                 : "r"(A[0]), "r"(A[1]), "r"(A[2]), "r"(A[3]),             \
                   "r"(B[0]), "r"(B[1]))

#define BK   16
#define LDP  20   // row stride (floats): 20 makes the 8 frag row-groups hit distinct banks

__global__ __launch_bounds__(256) void gemm_tc(const float* __restrict__ x,
                                               const float* __restrict__ W) {
    __shared__ uint32_t As[2][128 * LDP];   // [hi/lo][m * LDP + k]
    __shared__ uint32_t Bs[2][128 * LDP];   // [hi/lo][n * LDP + k]

    const int tid  = threadIdx.x;
    const int wid  = tid >> 5, lane = tid & 31;
    const int wm   = wid >> 1, wn = wid & 1;   // warp grid 4x2
    const int g    = lane >> 2, t = lane & 3;  // mma group / thread-in-group
    const int row0 = blockIdx.x * 128;

    float acc[2][8][4];
#pragma unroll
    for (int mt = 0; mt < 2; mt++)
#pragma unroll
        for (int nt = 0; nt < 8; nt++)
#pragma unroll
            for (int i = 0; i < 4; i++) acc[mt][nt][i] = 0.f;

    for (int k0 = 0; k0 < KIN; k0 += BK) {
        // Load + split x tile (128 x 16): 512 float4, 2 per thread
#pragma unroll
        for (int i = 0; i < 2; i++) {
            int f = tid + i * 256;
            int r = f >> 2, kk = (f & 3) << 2;
            float4 v = make_float4(0.f, 0.f, 0.f, 0.f);
            int gr = row0 + r;
            if (gr < NN) v = *(const float4*)(x + (size_t)gr * KIN + k0 + kk);
            int base = r * LDP + kk;
            uint32_t h0 = f2tf(v.x), h1 = f2tf(v.y), h2 = f2tf(v.z), h3 = f2tf(v.w);
            As[0][base + 0] = h0; As[0][base + 1] = h1;
            As[0][base + 2] = h2; As[0][base + 3] = h3;
            As[1][base + 0] = f2tf(v.x - __uint_as_float(h0));
            As[1][base + 1] = f2tf(v.y - __uint_as_float(h1));
            As[1][base + 2] = f2tf(v.z - __uint_as_float(h2));
            As[1][base + 3] = f2tf(v.w - __uint_as_float(h3));
        }
        // Load + split W tile (128 x 16)
#pragma unroll
        for (int i = 0; i < 2; i++) {
            int f = tid + i * 256;
            int r = f >> 2, kk = (f & 3) << 2;
            float4 v = *(const float4*)(W + (size_t)r * KIN + k0 + kk);
            int base = r * LDP + kk;
            uint32_t h0 = f2tf(v.x), h1 = f2tf(v.y), h2 = f2tf(v.z), h3 = f2tf(v.w);
            Bs[0][base + 0] = h0; Bs[0][base + 1] = h1;
            Bs[0][base + 2] = h2; Bs[0][base + 3] = h3;
            Bs[1][base + 0] = f2tf(v.x - __uint_as_float(h0));
            Bs[1][base + 1] = f2tf(v.y - __uint_as_float(h1));
            Bs[1][base + 2] = f2tf(v.z - __uint_as_float(h2));
            Bs[1][base + 3] = f2tf(v.w - __uint_as_float(h3));
        }
        __syncthreads();

#pragma unroll
        for (int ks = 0; ks < BK; ks += 8) {
            uint32_t ah[2][4], al[2][4];
#pragma unroll
            for (int mt = 0; mt < 2; mt++) {
                int base = (wm * 32 + mt * 16 + g) * LDP + ks + t;
                ah[mt][0] = As[0][base];            al[mt][0] = As[1][base];
                ah[mt][1] = As[0][base + 8 * LDP];  al[mt][1] = As[1][base + 8 * LDP];
                ah[mt][2] = As[0][base + 4];        al[mt][2] = As[1][base + 4];
                ah[mt][3] = As[0][base + 8 * LDP + 4]; al[mt][3] = As[1][base + 8 * LDP + 4];
            }
#pragma unroll
            for (int nt = 0; nt < 8; nt++) {
                int nb = (wn * 64 + nt * 8 + g) * LDP + ks + t;
                uint32_t bh[2], bl[2];
                bh[0] = Bs[0][nb]; bh[1] = Bs[0][nb + 4];
                bl[0] = Bs[1][nb]; bl[1] = Bs[1][nb + 4];
#pragma unroll
                for (int mt = 0; mt < 2; mt++) {
                    MMA_TF32(acc[mt][nt], ah[mt], bh);
                    MMA_TF32(acc[mt][nt], ah[mt], bl);
                    MMA_TF32(acc[mt][nt], al[mt], bh);
                }
            }
        }
        __syncthreads();
    }

    // Epilogue: C frag c0/c1 -> (row g, cols 2t,2t+1); c2/c3 -> row g+8
#pragma unroll
    for (int mt = 0; mt < 2; mt++) {
        int r = row0 + wm * 32 + mt * 16 + g;
#pragma unroll
        for (int nt = 0; nt < 8; nt++) {
            int col = wn * 64 + nt * 8 + 2 * t;
            if (r < NN)
                *(float2*)(g_h + (size_t)r * FOUT + col) =
                    make_float2(acc[mt][nt][0], acc[mt][nt][1]);
            if (r + 8 < NN)
                *(float2*)(g_h + (size_t)(r + 8) * FOUT + col) =
                    make_float2(acc[mt][nt][2], acc[mt][nt][3]);
        }
    }
}

// ---------------------------------------------------------------------------
// Kernel 2: per-node attention scores + self-loop init of accumulators.
// One warp per node. lane -> head = lane>>3, sub = lane&7 (4 channels each).
// out[i] = w_self * h[i];  den[i] = w_self;  also stores a_s, a_d.
// Block 0 also zeroes the BN stats accumulators (used two kernels later).
// ---------------------------------------------------------------------------
__global__ __launch_bounds__(256) void node_init_k(const float* __restrict__ att_src,
                                                   const float* __restrict__ att_dst,
                                                   float* __restrict__ out) {
    if (blockIdx.x == 0) g_stats[threadIdx.x] = 0.f;

    int warp = (blockIdx.x * blockDim.x + threadIdx.x) >> 5;
    int lane = threadIdx.x & 31;
    if (warp >= NN) return;
    int head = lane >> 3, sub = lane & 7;

    float4 hv  = *(const float4*)(g_h + (size_t)warp * FOUT + lane * 4);
    float4 as4 = *(const float4*)(att_src + head * 32 + sub * 4);
    float4 ad4 = *(const float4*)(att_dst + head * 32 + sub * 4);
    float ps = hv.x * as4.x + hv.y * as4.y + hv.z * as4.z + hv.w * as4.w;
    float pd = hv.x * ad4.x + hv.y * ad4.y + hv.z * ad4.z + hv.w * ad4.w;
#pragma unroll
    for (int o = 4; o; o >>= 1) {
        ps += __shfl_xor_sync(0xFFFFFFFFu, ps, o);
        pd += __shfl_xor_sync(0xFFFFFFFFu, pd, o);
    }
    float e = ps + pd;
    e = e < 0.f ? NEG_ATT * e : e;
    float w = __expf(e);

    *(float4*)(out + (size_t)warp * FOUT + lane * 4) =
        make_float4(w * hv.x, w * hv.y, w * hv.z, w * hv.w);
    if (sub == 0) {
        g_s[warp * 4 + head]   = ps;
        g_d[warp * 4 + head]   = pd;
        g_den[warp * 4 + head] = w;
    }
}

// ---------------------------------------------------------------------------
// Kernel 3: edge scatter. One warp per edge, vectorized RED.128 accumulation.
// ---------------------------------------------------------------------------
__global__ __launch_bounds__(256) void edge_k(const int* __restrict__ ei,
                                              float* __restrict__ out) {
    int warp = (int)((blockIdx.x * (unsigned)blockDim.x + threadIdx.x) >> 5);
    int lane = threadIdx.x & 31;
    if (warp >= EE) return;
    int src = ei[warp];
    int dst = ei[EE + warp];
    int head = lane >> 3;

    float e = g_s[src * 4 + head] + g_d[dst * 4 + head];
    e = e < 0.f ? NEG_ATT * e : e;
    float w = __expf(e);
    if ((lane & 7) == 0)
        atomicAdd(&g_den[dst * 4 + head], w);

    float4 hv = *(const float4*)(g_h + (size_t)src * FOUT + lane * 4);
    float* p = out + (size_t)dst * FOUT + lane * 4;
    asm volatile("red.global.add.v4.f32 [%0], {%1,%2,%3,%4};"
                 :: "l"(p), "f"(w * hv.x), "f"(w * hv.y),
                    "f"(w * hv.z), "f"(w * hv.w)
                 : "memory");
}

// ---------------------------------------------------------------------------
// Kernel 4: column-wise sum / sumsq of y = out/den + bias.
// ---------------------------------------------------------------------------
__global__ __launch_bounds__(128) void stats_k(const float* __restrict__ out,
                                               const float* __restrict__ bias) {
    int c = threadIdx.x;
    int rpb = (NN + gridDim.x - 1) / gridDim.x;
    int r0 = blockIdx.x * rpb;
    int r1 = min(r0 + rpb, NN);
    float b = bias[c];
    int hsel = c >> 5;
    float s = 0.f, ss = 0.f;
    for (int r = r0; r < r1; r++) {
        float y = out[(size_t)r * FOUT + c] / g_den[r * 4 + hsel] + b;
        s += y; ss += y * y;
    }
    atomicAdd(&g_stats[c], s);
    atomicAdd(&g_stats[128 + c], ss);
}

// ---------------------------------------------------------------------------
// Kernel 5: finalize — normalize, BN affine, LeakyReLU(0.01), in place.
// ---------------------------------------------------------------------------
__global__ __launch_bounds__(256) void final_k(float* __restrict__ out,
                                               const float* __restrict__ bias,
                                               const float* __restrict__ gamma,
                                               const float* __restrict__ beta) {
    size_t idx = (size_t)blockIdx.x * blockDim.x + threadIdx.x;
    if (idx >= (size_t)NN * FOUT) return;
    int c = (int)(idx & 127);
    size_t r = idx >> 7;
    float y = out[idx] / g_den[r * 4 + (c >> 5)] + bias[c];
    const float invN = 1.0f / NN;
    float mu  = g_stats[c] * invN;
    float var = g_stats[128 + c] * invN - mu * mu;
    float v = (y - mu) * rsqrtf(var + BN_EPS) * gamma[c] + beta[c];
    out[idx] = v < 0.f ? NEG_ACT * v : v;
}

// ---------------------------------------------------------------------------
extern "C" void kernel_launch(void* const* d_in, const int* in_sizes, int n_in,
                              void* d_out, int out_size) {
    const float* x       = (const float*)d_in[0];
    const int*   ei      = (const int*)  d_in[1];
    const float* W       = (const float*)d_in[2];
    const float* att_src = (const float*)d_in[3];
    const float* att_dst = (const float*)d_in[4];
    const float* bias    = (const float*)d_in[5];
    const float* gamma   = (const float*)d_in[6];
    const float* beta    = (const float*)d_in[7];
    float* out = (float*)d_out;

    gemm_tc<<<(NN + 127) / 128, 256>>>(x, W);
    node_init_k<<<(NN * 32 + 255) / 256, 256>>>(att_src, att_dst, out);
    edge_k<<<(EE * 32 + 255) / 256, 256>>>(ei, out);
    stats_k<<<512, 128>>>(out, bias);
    final_k<<<(int)(((size_t)NN * FOUT + 255) / 256), 256>>>(out, bias, gamma, beta);
}

// round 3
// speedup vs baseline: 1.2008x; 1.2008x over previous
#include <cuda_runtime.h>
#include <cuda_bf16.h>
#include <cstdint>

#define NN   50000
#define EE   800000
#define KIN  256
#define FOUT 128
#define NEG_ATT 0.2f
#define NEG_ACT 0.01f
#define BN_EPS  1e-5f

// Scratch (static device arrays — no allocations allowed)
__device__ __align__(16) float g_h[(size_t)NN * FOUT];   // projected features
__device__ __align__(16) float g_s[NN * 4];              // a_src per node/head
__device__ __align__(16) float g_d[NN * 4];              // a_dst per node/head
__device__ __align__(16) float g_den[NN * 4];            // softmax denominator
__device__ __align__(16) float g_dinv[NN * 4];           // 1 / denominator
__device__ __align__(16) float g_stats[256];             // col sum[128], sumsq[128]

// ---------------------------------------------------------------------------
// Kernel 1: h = x @ W^T   (64x128 block tile, BK=32, 4x8 register tile)
// ---------------------------------------------------------------------------
__global__ __launch_bounds__(256) void gemm_k(const float* __restrict__ x,
                                              const float* __restrict__ W) {
    __shared__ float As[32][68];    // [k][m], padded
    __shared__ float Bs[32][128];   // [k][n]
    const int row0 = blockIdx.x * 64;
    const int tid  = threadIdx.x;
    const int tr   = tid >> 4;      // 0..15 -> 4 rows each
    const int tc   = tid & 15;      // 0..15 -> 8 cols each

    float acc[4][8];
#pragma unroll
    for (int i = 0; i < 4; i++)
#pragma unroll
        for (int j = 0; j < 8; j++) acc[i][j] = 0.f;

    for (int k0 = 0; k0 < KIN; k0 += 32) {
#pragma unroll
        for (int i = 0; i < 2; i++) {
            int f = tid * 2 + i;
            int r = f >> 3, kk = (f & 7) << 2;
            int gr = row0 + r;
            float4 v = make_float4(0.f, 0.f, 0.f, 0.f);
            if (gr < NN) v = *(const float4*)(x + (size_t)gr * KIN + k0 + kk);
            As[kk + 0][r] = v.x; As[kk + 1][r] = v.y;
            As[kk + 2][r] = v.z; As[kk + 3][r] = v.w;
        }
#pragma unroll
        for (int i = 0; i < 4; i++) {
            int f = tid * 4 + i;
            int j = f >> 3, kk = (f & 7) << 2;
            float4 v = *(const float4*)(W + (size_t)j * KIN + k0 + kk);
            Bs[kk + 0][j] = v.x; Bs[kk + 1][j] = v.y;
            Bs[kk + 2][j] = v.z; Bs[kk + 3][j] = v.w;
        }
        __syncthreads();
#pragma unroll
        for (int k = 0; k < 32; k++) {
            float4 a  = *(const float4*)&As[k][tr * 4];
            float4 b0 = *(const float4*)&Bs[k][tc * 8];
            float4 b1 = *(const float4*)&Bs[k][tc * 8 + 4];
            float av[4] = {a.x, a.y, a.z, a.w};
            float bv[8] = {b0.x, b0.y, b0.z, b0.w, b1.x, b1.y, b1.z, b1.w};
#pragma unroll
            for (int i = 0; i < 4; i++)
#pragma unroll
                for (int j = 0; j < 8; j++) acc[i][j] += av[i] * bv[j];
        }
        __syncthreads();
    }
#pragma unroll
    for (int i = 0; i < 4; i++) {
        int gr = row0 + tr * 4 + i;
        if (gr < NN) {
            float* p = g_h + (size_t)gr * FOUT + tc * 8;
            *(float4*)(p)     = make_float4(acc[i][0], acc[i][1], acc[i][2], acc[i][3]);
            *(float4*)(p + 4) = make_float4(acc[i][4], acc[i][5], acc[i][6], acc[i][7]);
        }
    }
}

// ---------------------------------------------------------------------------
// Kernel 2: per-node attention scores + self-loop init of accumulators.
// One warp per node. Block 0 also zeroes the BN stats accumulators.
// ---------------------------------------------------------------------------
__global__ __launch_bounds__(256) void node_init_k(const float* __restrict__ att_src,
                                                   const float* __restrict__ att_dst,
                                                   float* __restrict__ out) {
    if (blockIdx.x == 0) g_stats[threadIdx.x] = 0.f;

    int warp = (blockIdx.x * blockDim.x + threadIdx.x) >> 5;
    int lane = threadIdx.x & 31;
    if (warp >= NN) return;
    int head = lane >> 3, sub = lane & 7;

    float4 hv  = *(const float4*)(g_h + (size_t)warp * FOUT + lane * 4);
    float4 as4 = *(const float4*)(att_src + head * 32 + sub * 4);
    float4 ad4 = *(const float4*)(att_dst + head * 32 + sub * 4);
    float ps = hv.x * as4.x + hv.y * as4.y + hv.z * as4.z + hv.w * as4.w;
    float pd = hv.x * ad4.x + hv.y * ad4.y + hv.z * ad4.z + hv.w * ad4.w;
#pragma unroll
    for (int o = 4; o; o >>= 1) {
        ps += __shfl_xor_sync(0xFFFFFFFFu, ps, o);
        pd += __shfl_xor_sync(0xFFFFFFFFu, pd, o);
    }
    float e = ps + pd;
    e = e < 0.f ? NEG_ATT * e : e;
    float w = __expf(e);

    *(float4*)(out + (size_t)warp * FOUT + lane * 4) =
        make_float4(w * hv.x, w * hv.y, w * hv.z, w * hv.w);
    if (sub == 0) {
        g_s[warp * 4 + head]   = ps;
        g_d[warp * 4 + head]   = pd;
        g_den[warp * 4 + head] = w;
    }
}

// ---------------------------------------------------------------------------
// Kernel 3: edge scatter. One warp per edge, vectorized RED.128 accumulation.
// ---------------------------------------------------------------------------
__global__ __launch_bounds__(256) void edge_k(const int* __restrict__ ei,
                                              float* __restrict__ out) {
    int warp = (int)((blockIdx.x * (unsigned)blockDim.x + threadIdx.x) >> 5);
    int lane = threadIdx.x & 31;
    if (warp >= EE) return;
    int src = ei[warp];
    int dst = ei[EE + warp];
    int head = lane >> 3;

    float e = g_s[src * 4 + head] + g_d[dst * 4 + head];
    e = e < 0.f ? NEG_ATT * e : e;
    float w = __expf(e);
    if ((lane & 7) == 0)
        atomicAdd(&g_den[dst * 4 + head], w);

    float4 hv = *(const float4*)(g_h + (size_t)src * FOUT + lane * 4);
    float* p = out + (size_t)dst * FOUT + lane * 4;
    asm volatile("red.global.add.v4.f32 [%0], {%1,%2,%3,%4};"
                 :: "l"(p), "f"(w * hv.x), "f"(w * hv.y),
                    "f"(w * hv.z), "f"(w * hv.w)
                 : "memory");
}

// ---------------------------------------------------------------------------
// Kernel 3b: reciprocal of the softmax denominator (200K elems, one pass).
// Replaces 12.8M fp32 divisions in stats/final with multiplies.
// ---------------------------------------------------------------------------
__global__ __launch_bounds__(256) void inv_k() {
    int i = blockIdx.x * blockDim.x + threadIdx.x;
    if (i < NN * 4) g_dinv[i] = 1.0f / g_den[i];
}

// ---------------------------------------------------------------------------
// Kernel 4: column-wise sum / sumsq of y = out*dinv + bias.
// Row-strided blocks (coalesced 512B rows), unroll-4 for MLP.
// ---------------------------------------------------------------------------
__global__ __launch_bounds__(128) void stats_k(const float* __restrict__ out,
                                               const float* __restrict__ bias) {
    const int c = threadIdx.x;
    const float b = bias[c];
    const int hsel = c >> 5;
    float s0 = 0.f, s1 = 0.f, q0 = 0.f, q1 = 0.f;

    int r = blockIdx.x;
    const int stride = gridDim.x;
    for (; r + 3 * stride < NN; r += 4 * stride) {
        float y0 = fmaf(out[(size_t)(r)              * FOUT + c], g_dinv[(r)              * 4 + hsel], b);
        float y1 = fmaf(out[(size_t)(r + stride)     * FOUT + c], g_dinv[(r + stride)     * 4 + hsel], b);
        float y2 = fmaf(out[(size_t)(r + 2 * stride) * FOUT + c], g_dinv[(r + 2 * stride) * 4 + hsel], b);
        float y3 = fmaf(out[(size_t)(r + 3 * stride) * FOUT + c], g_dinv[(r + 3 * stride) * 4 + hsel], b);
        s0 += y0 + y1; s1 += y2 + y3;
        q0 = fmaf(y0, y0, fmaf(y1, y1, q0));
        q1 = fmaf(y2, y2, fmaf(y3, y3, q1));
    }
    for (; r < NN; r += stride) {
        float y = fmaf(out[(size_t)r * FOUT + c], g_dinv[r * 4 + hsel], b);
        s0 += y; q0 = fmaf(y, y, q0);
    }
    atomicAdd(&g_stats[c], s0 + s1);
    atomicAdd(&g_stats[128 + c], q0 + q1);
}

// ---------------------------------------------------------------------------
// Kernel 5: finalize — normalize, BN affine, LeakyReLU(0.01), float4 in place.
// ---------------------------------------------------------------------------
__global__ __launch_bounds__(256) void final_k(float* __restrict__ out,
                                               const float* __restrict__ bias,
                                               const float* __restrict__ gamma,
                                               const float* __restrict__ beta) {
    size_t idx = (size_t)blockIdx.x * blockDim.x + threadIdx.x;     // over N*32
    if (idx >= (size_t)NN * 32) return;
    int cq = (int)(idx & 31);          // float4 group within row
    size_t r = idx >> 5;
    int c = cq * 4;
    float di = g_dinv[r * 4 + (c >> 5)];

    float4 v = *(float4*)(out + r * FOUT + c);
    const float invN = 1.0f / NN;
    float y[4] = {v.x, v.y, v.z, v.w};
#pragma unroll
    for (int j = 0; j < 4; j++) {
        int cc = c + j;
        float yy = fmaf(y[j], di, bias[cc]);
        float mu  = g_stats[cc] * invN;
        float var = fmaf(g_stats[128 + cc], invN, -mu * mu);
        float z = (yy - mu) * rsqrtf(var + BN_EPS) * gamma[cc] + beta[cc];
        y[j] = z < 0.f ? NEG_ACT * z : z;
    }
    *(float4*)(out + r * FOUT + c) = make_float4(y[0], y[1], y[2], y[3]);
}

// ---------------------------------------------------------------------------
extern "C" void kernel_launch(void* const* d_in, const int* in_sizes, int n_in,
                              void* d_out, int out_size) {
    const float* x       = (const float*)d_in[0];
    const int*   ei      = (const int*)  d_in[1];
    const float* W       = (const float*)d_in[2];
    const float* att_src = (const float*)d_in[3];
    const float* att_dst = (const float*)d_in[4];
    const float* bias    = (const float*)d_in[5];
    const float* gamma   = (const float*)d_in[6];
    const float* beta    = (const float*)d_in[7];
    float* out = (float*)d_out;

    gemm_k<<<(NN + 63) / 64, 256>>>(x, W);
    node_init_k<<<(NN * 32 + 255) / 256, 256>>>(att_src, att_dst, out);
    edge_k<<<(EE * 32 + 255) / 256, 256>>>(ei, out);
    inv_k<<<(NN * 4 + 255) / 256, 256>>>();
    stats_k<<<2048, 128>>>(out, bias);
    final_k<<<(int)(((size_t)NN * 32 + 255) / 256), 256>>>(out, bias, gamma, beta);
}